// round 14
// baseline (speedup 1.0000x reference)
#include <cuda_runtime.h>
#include <cuda_bf16.h>
#include <cstddef>

#define BB   1024
#define TT   336
#define II   16
#define HH   64
#define GG   256

#define LBLK  148
#define RMAX  7
#define NB7   136

__device__ float g_xp[(size_t)TT * BB * GG];   // layer-1 input projections (biases included)
__device__ float g_h1[(size_t)TT * BB * HH];   // layer-0 hidden outputs
__device__ float g_h2[(size_t)BB * HH];        // layer-1 last hidden

__device__ __forceinline__ float sigf(float x) { return 1.0f / (1.0f + __expf(-x)); }
__device__ __forceinline__ float tanh_fast(float x) {
    x = fminf(fmaxf(x, -15.0f), 15.0f);
    float E = __expf(2.0f * x);
    return __fdividef(E - 1.0f, E + 1.0f);
}

typedef unsigned long long u64;
__device__ __forceinline__ u64 pack2(float lo, float hi) {
    u64 r; asm("mov.b64 %0, {%1, %2};" : "=l"(r) : "f"(lo), "f"(hi)); return r;
}
__device__ __forceinline__ void unpack2(u64 v, float& lo, float& hi) {
    asm("mov.b64 {%0, %1}, %2;" : "=f"(lo), "=f"(hi) : "l"(v));
}
__device__ __forceinline__ u64 fma2(u64 a, u64 b, u64 c) {
    u64 d; asm("fma.rn.f32x2 %0, %1, %2, %3;" : "=l"(d) : "l"(a), "l"(b), "l"(c)); return d;
}
__device__ __forceinline__ float hsum2(u64 a) {
    float lo, hi; unpack2(a, lo, hi); return lo + hi;
}

// ---------------------------------------------------------------------------
// LSTM recurrence, 512 threads, G=2 gates/thread, S=16 K-slice (4 slices).
// Phase-1 thread (gg = tid&127 -> gates 2gg,2gg+1; q = tid>>7 -> K-slice):
//   pure recurrent GEMM partial over RMAX rows; h broadcast LDS.128 (28/thread,
//   HALF of the R8 design); weights in regs. L0 additionally folds the K=16
//   input projection (x staged in smem by 28 loader threads, double-buffered).
// Phase-2 thread (tid<448; r=tid>>6, u=tid&63): sums 4 partials (16 LDS.32),
//   adds xp (L1: 4 coalesced LDG.32 issued at loop top, covered by phase 1)
//   or bias (L0), activations, c in reg, h_s + g_h1/g_h2.
// Two barriers/step. Phantom 7th row in 6-row blocks: computed, never consumed.
// ---------------------------------------------------------------------------
template <int LAYER>
__global__ void __launch_bounds__(512, 1) lstm_fused(const float* __restrict__ x,
                                                     const float* __restrict__ Wih,
                                                     const float* __restrict__ Whh,
                                                     const float* __restrict__ bih,
                                                     const float* __restrict__ bhh) {
    __shared__ __align__(16) float h_s[RMAX * HH];        // 1.75KB
    __shared__ __align__(16) float gP[4][RMAX * GG];      // 28KB
    __shared__ __align__(16) float xstage[2][RMAX][II];   // 896B (L0 only)

    const int tid = threadIdx.x;
    const int gg = tid & 127;
    const int q  = tid >> 7;          // K-slice 0..3
    const int g0 = gg * 2;            // first of this thread's two gates
    const int bid = blockIdx.x;
    const int rows = (bid < NB7) ? 7 : 6;
    const int b0 = (bid < NB7) ? bid * 7 : NB7 * 7 + (bid - NB7) * 6;

    // recurrent weights: 2 gates x 16 floats -> 8 u64 pairs each
    u64 wh0[8], wh1[8];
    {
        const ulonglong2* W0 = reinterpret_cast<const ulonglong2*>(Whh + (size_t)g0 * HH + q * 16);
        const ulonglong2* W1 = reinterpret_cast<const ulonglong2*>(Whh + (size_t)(g0 + 1) * HH + q * 16);
        #pragma unroll
        for (int k = 0; k < 4; ++k) {
            ulonglong2 a = W0[k]; wh0[2*k] = a.x; wh0[2*k+1] = a.y;
            ulonglong2 b = W1[k]; wh1[2*k] = b.x; wh1[2*k+1] = b.y;
        }
    }
    // L0: input-proj weights, 2 gates x 4 floats (this slice's quarter of K=16)
    u64 wi00 = 0, wi01 = 0, wi10 = 0, wi11 = 0;
    if (LAYER == 0) {
        ulonglong2 a = *reinterpret_cast<const ulonglong2*>(Wih + (size_t)g0 * II + q * 4);
        ulonglong2 b = *reinterpret_cast<const ulonglong2*>(Wih + (size_t)(g0 + 1) * II + q * 4);
        wi00 = a.x; wi01 = a.y; wi10 = b.x; wi11 = b.y;
    }

    for (int idx = tid; idx < RMAX * HH; idx += 512) h_s[idx] = 0.0f;

    // phase-2 role
    const int r2 = tid >> 6;
    const int u2 = tid & 63;
    const bool p2 = (tid < RMAX * 64) && (r2 < rows);
    const int r2c = (r2 < RMAX) ? r2 : 0;
    float* const p2h  = h_s + r2c * HH + u2;
    float* const p2g1 = g_h1 + (size_t)(b0 + r2c) * HH + u2;
    float* const p2g2 = g_h2 + (size_t)(b0 + r2c) * HH + u2;
    const float* const xpbase = g_xp + (size_t)(b0 + r2c) * GG + u2;   // + t*BB*GG
    float bs2[4] = {0.f, 0.f, 0.f, 0.f};
    if (LAYER == 0 && tid < RMAX * 64) {
        #pragma unroll
        for (int j = 0; j < 4; ++j) bs2[j] = bih[u2 + 64 * j] + bhh[u2 + 64 * j];
    }
    float c = 0.0f;

    // L0 x-stagers: 28 threads, disjoint from phase-2 threads
    const bool loader = (LAYER == 0) && (tid >= 448) && (tid < 448 + 28);
    const float* lsrc = nullptr;
    float* ldst0 = nullptr; float* ldst1 = nullptr;
    if (loader) {
        const int j = tid - 448;
        const int row = j >> 2, col4 = (j & 3) << 2;
        int brow = b0 + row; if (brow > BB - 1) brow = BB - 1;
        lsrc = x + ((size_t)brow * TT) * II + col4;
        ldst0 = &xstage[0][row][col4];
        ldst1 = &xstage[1][row][col4];
        *reinterpret_cast<float4*>(ldst0) = *reinterpret_cast<const float4*>(lsrc);
    }

    __syncthreads();

    #pragma unroll 1
    for (int t = 0; t < TT; ++t) {
        // L1: issue this step's xp loads now; DRAM latency covered by phase 1
        float xp4[4];
        if (LAYER == 1 && p2) {
            const float* src = xpbase + (size_t)t * BB * GG;
            #pragma unroll
            for (int j = 0; j < 4; ++j) xp4[j] = src[64 * j];
        }
        // L0: prefetch x[t+1]
        float4 lv;
        const bool doload = loader && (t + 1 < TT);
        if (doload) lv = *reinterpret_cast<const float4*>(lsrc + (size_t)(t + 1) * II);

        u64 acc0[RMAX], acc1[RMAX];
        #pragma unroll
        for (int b = 0; b < RMAX; ++b) { acc0[b] = 0ull; acc1[b] = 0ull; }

        if (LAYER == 0) {
            const float* const xr = &xstage[t & 1][0][0];
            #pragma unroll
            for (int b = 0; b < RMAX; ++b) {
                ulonglong2 xv = *reinterpret_cast<const ulonglong2*>(xr + b * II + q * 4);
                acc0[b] = fma2(xv.x, wi00, acc0[b]);
                acc0[b] = fma2(xv.y, wi01, acc0[b]);
                acc1[b] = fma2(xv.x, wi10, acc1[b]);
                acc1[b] = fma2(xv.y, wi11, acc1[b]);
            }
        }

        // recurrent K-slice: 1 LDS.128 + 4 fma2 per (k,b)
        const float* const hb = h_s + q * 16;
        #pragma unroll
        for (int k = 0; k < 4; ++k) {
            const u64 wa0 = wh0[2*k], wa1 = wh0[2*k+1];
            const u64 wb0 = wh1[2*k], wb1 = wh1[2*k+1];
            #pragma unroll
            for (int b = 0; b < RMAX; ++b) {
                ulonglong2 h2 = *reinterpret_cast<const ulonglong2*>(hb + b * HH + k * 4);
                acc0[b] = fma2(h2.x, wa0, acc0[b]);
                acc0[b] = fma2(h2.y, wa1, acc0[b]);
                acc1[b] = fma2(h2.x, wb0, acc1[b]);
                acc1[b] = fma2(h2.y, wb1, acc1[b]);
            }
        }
        {
            float* gp = gP[q] + g0;
            #pragma unroll
            for (int b = 0; b < RMAX; ++b) {
                float2 pv = make_float2(hsum2(acc0[b]), hsum2(acc1[b]));
                *reinterpret_cast<float2*>(gp + b * GG) = pv;
            }
        }
        if (doload) *((t & 1) ? reinterpret_cast<float4*>(ldst0)
                              : reinterpret_cast<float4*>(ldst1)) = lv;
        __syncthreads();   // H1: partials (and staged x) visible

        if (p2) {
            float s[4];
            #pragma unroll
            for (int j = 0; j < 4; ++j) {
                const int o = r2 * GG + u2 + 64 * j;
                s[j] = (gP[0][o] + gP[1][o]) + (gP[2][o] + gP[3][o]);
                s[j] += (LAYER == 0) ? bs2[j] : xp4[j];
            }
            float iv = sigf(s[0]);
            float fv = sigf(s[1]);
            float gv = tanh_fast(s[2]);
            float ov = sigf(s[3]);
            float cn = fmaf(fv, c, iv * gv);
            c = cn;
            float hn = ov * tanh_fast(cn);
            *p2h = hn;
            if (LAYER == 0) p2g1[(size_t)t * BB * HH] = hn;
            else if (t == TT - 1) *p2g2 = hn;
        }
        __syncthreads();   // H2: h updated before next step
    }
}

// ---------------------------------------------------------------------------
// proj1: g_xp[t][b][g] = sum_j g_h1[t][b][j] * Wih1[g][j] + bih1[g] + bhh1[g]
// ---------------------------------------------------------------------------
#define P1P 64
__global__ void __launch_bounds__(256) proj1_kernel(const float* __restrict__ Wih,
                                                    const float* __restrict__ bih,
                                                    const float* __restrict__ bhh) {
    __shared__ __align__(16) float hs[P1P * HH];
    const int tid = threadIdx.x;
    const int g = tid;
    const float bsum = bih[g] + bhh[g];

    const int n0 = blockIdx.x * P1P;
    {
        const float4* src = reinterpret_cast<const float4*>(g_h1 + (size_t)n0 * HH);
        float4* dst = reinterpret_cast<float4*>(hs);
        #pragma unroll 4
        for (int idx = tid; idx < (P1P * HH) / 4; idx += 256) dst[idx] = src[idx];
    }
    u64 w2[32];
    {
        const ulonglong2* Wv = reinterpret_cast<const ulonglong2*>(Wih + (size_t)g * HH);
        #pragma unroll
        for (int k = 0; k < 16; ++k) { ulonglong2 v = Wv[k]; w2[2*k] = v.x; w2[2*k+1] = v.y; }
    }
    __syncthreads();

    #pragma unroll 2
    for (int p = 0; p < P1P; ++p) {
        const ulonglong2* hv = reinterpret_cast<const ulonglong2*>(hs + p * HH);
        u64 accA = pack2(bsum, 0.0f), accB = 0ull;
        #pragma unroll
        for (int k = 0; k < 16; ++k) {
            ulonglong2 h2 = hv[k];
            accA = fma2(h2.x, w2[2*k],   accA);
            accB = fma2(h2.y, w2[2*k+1], accB);
        }
        g_xp[(size_t)(n0 + p) * GG + g] = hsum2(accA) + hsum2(accB);
    }
}

__global__ void __launch_bounds__(128) fc_kernel(const float* __restrict__ Wfc,
                                                 const float* __restrict__ bfc,
                                                 float* __restrict__ out) {
    __shared__ float w_s[HH];
    const int tid = threadIdx.x;
    if (tid < HH) w_s[tid] = Wfc[tid];
    __syncthreads();
    const int b = blockIdx.x * 128 + tid;
    if (b < BB) {
        const float* hp = g_h2 + (size_t)b * HH;
        float a = bfc[0];
        #pragma unroll
        for (int j = 0; j < HH; ++j) a = fmaf(hp[j], w_s[j], a);
        out[b] = a;
    }
}

extern "C" void kernel_launch(void* const* d_in, const int* in_sizes, int n_in,
                              void* d_out, int out_size) {
    const float* x    = (const float*)d_in[0];
    const float* Wih0 = (const float*)d_in[1];
    const float* Whh0 = (const float*)d_in[2];
    const float* bih0 = (const float*)d_in[3];
    const float* bhh0 = (const float*)d_in[4];
    const float* Wih1 = (const float*)d_in[5];
    const float* Whh1 = (const float*)d_in[6];
    const float* bih1 = (const float*)d_in[7];
    const float* bhh1 = (const float*)d_in[8];
    const float* Wfc  = (const float*)d_in[9];
    const float* bfc  = (const float*)d_in[10];
    float* out = (float*)d_out;

    lstm_fused<0><<<LBLK, 512>>>(x, Wih0, Whh0, bih0, bhh0);
    proj1_kernel<<<(TT * BB) / P1P, 256>>>(Wih1, bih1, bhh1);
    lstm_fused<1><<<LBLK, 512>>>(nullptr, nullptr, Whh1, nullptr, nullptr);
    fc_kernel<<<(BB + 127) / 128, 128>>>(Wfc, bfc, out);
}

// round 15
// speedup vs baseline: 1.4858x; 1.4858x over previous
#include <cuda_runtime.h>
#include <cuda_bf16.h>
#include <cstddef>

#define BB   1024
#define TT   336
#define II   16
#define HH   64
#define GG   256

// LSTM: 296 CTAs (2 per SM), 136 x 4 rows + 160 x 3 rows = 1024
#define LBLK2 296
#define NB4   136
#define RMX   4

__device__ float g_xp[(size_t)TT * BB * GG];   // layer-1 input projections (biases included)
__device__ float g_h1[(size_t)TT * BB * HH];   // layer-0 hidden outputs
__device__ float g_h2[(size_t)BB * HH];        // layer-1 last hidden

__device__ __forceinline__ float sigf(float x) { return 1.0f / (1.0f + __expf(-x)); }
__device__ __forceinline__ float tanh_fast(float x) {
    x = fminf(fmaxf(x, -15.0f), 15.0f);
    float E = __expf(2.0f * x);
    return __fdividef(E - 1.0f, E + 1.0f);
}

typedef unsigned long long u64;
__device__ __forceinline__ u64 pack2(float lo, float hi) {
    u64 r; asm("mov.b64 %0, {%1, %2};" : "=l"(r) : "f"(lo), "f"(hi)); return r;
}
__device__ __forceinline__ u64 fma2(u64 a, u64 b, u64 c) {
    u64 d; asm("fma.rn.f32x2 %0, %1, %2, %3;" : "=l"(d) : "l"(a), "l"(b), "l"(c)); return d;
}
__device__ __forceinline__ float hsum2(u64 a) {
    float lo, hi; asm("mov.b64 {%0, %1}, %2;" : "=f"(lo), "=f"(hi) : "l"(a));
    return lo + hi;
}

// ---------------------------------------------------------------------------
// LSTM recurrence: 256 threads/CTA, 2 CTAs/SM (independent barrier domains),
// 4 rows per CTA (last 160 CTAs: 3 rows + 1 phantom).
// Phase 1 (all 256 threads): thread g computes the COMPLETE gate-g
//   pre-activation for all 4 rows: full K=64 dot (Whh in 32 u64 regs, h
//   broadcast LDS.128) + [L0] fused K=16 input proj (x staged in smem)
//   + bias (L0) or xp (L1, register-prefetched 2 steps ahead). One STS/row.
// Phase 2 (tid < rows*64): one (row,unit)/thread: 4 LDS.32, activations,
//   c in reg, h_s (+ g_h1 every step for L0 / g_h2 last step for L1).
// Two barriers/step per CTA; co-resident CTA fills the stall gaps.
// ---------------------------------------------------------------------------
template <int LAYER>
__global__ void __launch_bounds__(256, 2) lstm2(const float* __restrict__ x,
                                                const float* __restrict__ Wih,
                                                const float* __restrict__ Whh,
                                                const float* __restrict__ bih,
                                                const float* __restrict__ bhh) {
    __shared__ __align__(16) float h_s[RMX * HH];       // 1KB
    __shared__ __align__(16) float gsum[RMX * GG];      // 4KB
    __shared__ __align__(16) float xst[2][RMX][II];     // 512B (L0 only)

    const int tid = threadIdx.x;
    const int g = tid;
    const int bid = blockIdx.x;
    const int rows = (bid < NB4) ? 4 : 3;
    const int b0 = (bid < NB4) ? bid * 4 : NB4 * 4 + (bid - NB4) * 3;

    // full-K recurrent weights: 64 floats -> 32 u64 pairs
    u64 wh[32];
    {
        const ulonglong2* Wv = reinterpret_cast<const ulonglong2*>(Whh + (size_t)g * HH);
        #pragma unroll
        for (int k = 0; k < 16; ++k) { ulonglong2 v = Wv[k]; wh[2*k] = v.x; wh[2*k+1] = v.y; }
    }
    // L0: input-proj weights (16 floats -> 8 pairs) + bias
    u64 wi[8]; float bsum = 0.0f;
    if (LAYER == 0) {
        const ulonglong2* Wv = reinterpret_cast<const ulonglong2*>(Wih + (size_t)g * II);
        #pragma unroll
        for (int k = 0; k < 4; ++k) { ulonglong2 v = Wv[k]; wi[2*k] = v.x; wi[2*k+1] = v.y; }
        bsum = bih[g] + bhh[g];
    }

    h_s[tid] = 0.0f;   // 256 = RMX*HH exactly

    // per-row g_xp offsets (phantom clamped)
    size_t rowoff[RMX];
    #pragma unroll
    for (int b = 0; b < RMX; ++b) {
        int rr = b0 + b; if (rr > BB - 1) rr = BB - 1;
        rowoff[b] = (size_t)rr * GG;
    }
    const size_t stepStride = (size_t)BB * GG;
    const float* xpp = g_xp + g;

    // L1: xp register pipeline, 2 steps ahead
    float xp_cur[RMX], xp_nxt[RMX];
    if (LAYER == 1) {
        #pragma unroll
        for (int b = 0; b < RMX; ++b) xp_cur[b] = xpp[rowoff[b]];
        #pragma unroll
        for (int b = 0; b < RMX; ++b) xp_nxt[b] = xpp[stepStride + rowoff[b]];
    }

    // L0: x stagers (16 threads; they also do phase-1/phase-2 work)
    const bool loader = (LAYER == 0) && (tid < 16);
    const float* lsrc = nullptr;
    float* ldst0 = nullptr; float* ldst1 = nullptr;
    if (loader) {
        const int row = tid >> 2, col4 = (tid & 3) << 2;
        int brow = b0 + row; if (brow > BB - 1) brow = BB - 1;
        lsrc = x + ((size_t)brow * TT) * II + col4;
        ldst0 = &xst[0][row][col4];
        ldst1 = &xst[1][row][col4];
        *reinterpret_cast<float4*>(ldst0) = *reinterpret_cast<const float4*>(lsrc);
    }

    // phase-2 role
    const int r2 = tid >> 6;
    const int u2 = tid & 63;
    const bool p2 = (r2 < rows);
    float* const p2h  = h_s + r2 * HH + u2;
    const int brow2 = (b0 + r2 < BB) ? (b0 + r2) : (BB - 1);
    float* const p2g1 = g_h1 + (size_t)brow2 * HH + u2;
    float* const p2g2 = g_h2 + (size_t)brow2 * HH + u2;
    float c = 0.0f;

    __syncthreads();

    #pragma unroll 1
    for (int t = 0; t < TT; ++t) {
        // L0: prefetch x[t+1]
        float4 lv;
        const bool doload = loader && (t + 1 < TT);
        if (doload) lv = *reinterpret_cast<const float4*>(lsrc + (size_t)(t + 1) * II);

        u64 acc[RMX];
        #pragma unroll
        for (int b = 0; b < RMX; ++b)
            acc[b] = pack2((LAYER == 0) ? bsum : xp_cur[b], 0.0f);

        if (LAYER == 1) {
            #pragma unroll
            for (int b = 0; b < RMX; ++b) xp_cur[b] = xp_nxt[b];
            if (t + 2 < TT) {
                const float* src = xpp + (size_t)(t + 2) * stepStride;
                #pragma unroll
                for (int b = 0; b < RMX; ++b) xp_nxt[b] = src[rowoff[b]];
            }
        }

        if (LAYER == 0) {
            // fused input projection (K=16): 2 LDS.128 + 8 fma2 per row
            #pragma unroll
            for (int b = 0; b < RMX; ++b) {
                const ulonglong2* xv = reinterpret_cast<const ulonglong2*>(&xst[t & 1][b][0]);
                ulonglong2 v0 = xv[0], v1 = xv[1];
                acc[b] = fma2(v0.x, wi[0], acc[b]);
                acc[b] = fma2(v0.y, wi[1], acc[b]);
                acc[b] = fma2(v1.x, wi[2], acc[b]);
                acc[b] = fma2(v1.y, wi[3], acc[b]);
                // second 8 floats
                const ulonglong2* xv2 = xv + 2;
                (void)xv2;
                ulonglong2 v2 = xv[2], v3 = xv[3];
                acc[b] = fma2(v2.x, wi[4], acc[b]);
                acc[b] = fma2(v2.y, wi[5], acc[b]);
                acc[b] = fma2(v3.x, wi[6], acc[b]);
                acc[b] = fma2(v3.y, wi[7], acc[b]);
            }
        }

        // full-K recurrent GEMM: 16 LDS.128 + 32 fma2 per row
        #pragma unroll
        for (int k = 0; k < 16; ++k) {
            const u64 wA = wh[2*k], wB = wh[2*k+1];
            #pragma unroll
            for (int b = 0; b < RMX; ++b) {
                ulonglong2 h2 = *reinterpret_cast<const ulonglong2*>(h_s + b * HH + k * 4);
                acc[b] = fma2(h2.x, wA, acc[b]);
                acc[b] = fma2(h2.y, wB, acc[b]);
            }
        }
        #pragma unroll
        for (int b = 0; b < RMX; ++b) gsum[b * GG + g] = hsum2(acc[b]);

        if (doload) *((t & 1) ? reinterpret_cast<float4*>(ldst0)
                              : reinterpret_cast<float4*>(ldst1)) = lv;
        __syncthreads();   // H1: gates (and staged x) visible

        if (p2) {
            const float* gr = gsum + r2 * GG + u2;
            float s0 = gr[0], s1 = gr[64], s2 = gr[128], s3 = gr[192];
            float iv = sigf(s0);
            float fv = sigf(s1);
            float gv = tanh_fast(s2);
            float ov = sigf(s3);
            float cn = fmaf(fv, c, iv * gv);
            c = cn;
            float hn = ov * tanh_fast(cn);
            *p2h = hn;
            if (LAYER == 0) p2g1[(size_t)t * BB * HH] = hn;
            else if (t == TT - 1) *p2g2 = hn;
        }
        __syncthreads();   // H2: h updated before next step
    }
}

// ---------------------------------------------------------------------------
// proj1: g_xp[t][b][g] = sum_j g_h1[t][b][j] * Wih1[g][j] + bih1[g] + bhh1[g]
// ---------------------------------------------------------------------------
#define P1P 64
__global__ void __launch_bounds__(256) proj1_kernel(const float* __restrict__ Wih,
                                                    const float* __restrict__ bih,
                                                    const float* __restrict__ bhh) {
    __shared__ __align__(16) float hs[P1P * HH];
    const int tid = threadIdx.x;
    const int g = tid;
    const float bsum = bih[g] + bhh[g];

    const int n0 = blockIdx.x * P1P;
    {
        const float4* src = reinterpret_cast<const float4*>(g_h1 + (size_t)n0 * HH);
        float4* dst = reinterpret_cast<float4*>(hs);
        #pragma unroll 4
        for (int idx = tid; idx < (P1P * HH) / 4; idx += 256) dst[idx] = src[idx];
    }
    u64 w2[32];
    {
        const ulonglong2* Wv = reinterpret_cast<const ulonglong2*>(Wih + (size_t)g * HH);
        #pragma unroll
        for (int k = 0; k < 16; ++k) { ulonglong2 v = Wv[k]; w2[2*k] = v.x; w2[2*k+1] = v.y; }
    }
    __syncthreads();

    #pragma unroll 2
    for (int p = 0; p < P1P; ++p) {
        const ulonglong2* hv = reinterpret_cast<const ulonglong2*>(hs + p * HH);
        u64 accA = pack2(bsum, 0.0f), accB = 0ull;
        #pragma unroll
        for (int k = 0; k < 16; ++k) {
            ulonglong2 h2 = hv[k];
            accA = fma2(h2.x, w2[2*k],   accA);
            accB = fma2(h2.y, w2[2*k+1], accB);
        }
        g_xp[(size_t)(n0 + p) * GG + g] = hsum2(accA) + hsum2(accB);
    }
}

__global__ void __launch_bounds__(128) fc_kernel(const float* __restrict__ Wfc,
                                                 const float* __restrict__ bfc,
                                                 float* __restrict__ out) {
    __shared__ float w_s[HH];
    const int tid = threadIdx.x;
    if (tid < HH) w_s[tid] = Wfc[tid];
    __syncthreads();
    const int b = blockIdx.x * 128 + tid;
    if (b < BB) {
        const float* hp = g_h2 + (size_t)b * HH;
        float a = bfc[0];
        #pragma unroll
        for (int j = 0; j < HH; ++j) a = fmaf(hp[j], w_s[j], a);
        out[b] = a;
    }
}

extern "C" void kernel_launch(void* const* d_in, const int* in_sizes, int n_in,
                              void* d_out, int out_size) {
    const float* x    = (const float*)d_in[0];
    const float* Wih0 = (const float*)d_in[1];
    const float* Whh0 = (const float*)d_in[2];
    const float* bih0 = (const float*)d_in[3];
    const float* bhh0 = (const float*)d_in[4];
    const float* Wih1 = (const float*)d_in[5];
    const float* Whh1 = (const float*)d_in[6];
    const float* bih1 = (const float*)d_in[7];
    const float* bhh1 = (const float*)d_in[8];
    const float* Wfc  = (const float*)d_in[9];
    const float* bfc  = (const float*)d_in[10];
    float* out = (float*)d_out;

    // layer 0: fused input projection + recurrence, 2 CTAs/SM
    lstm2<0><<<LBLK2, 256>>>(x, Wih0, Whh0, bih0, bhh0);
    // layer 1 input projection
    proj1_kernel<<<(TT * BB) / P1P, 256>>>(Wih1, bih1, bhh1);
    // layer 1: recurrence, 2 CTAs/SM
    lstm2<1><<<LBLK2, 256>>>(nullptr, nullptr, Whh1, nullptr, nullptr);
    // final FC
    fc_kernel<<<(BB + 127) / 128, 128>>>(Wfc, bfc, out);
}